// round 13
// baseline (speedup 1.0000x reference)
#include <cuda_runtime.h>

#define T_SEQ 128
#define BATCH 256
#define F_IN  2048
#define F_HID 1024
#define F_OUT 20

// Arm 2 panel constants (Eigen single-thread blocking with Grace L1d=64KB):
#define KC2_1024 520
#define KC2_2048 688

// ---------------- device scratch (no allocations allowed) ----------------
__device__ float g_zin[(size_t)T_SEQ * BATCH * F_HID];
__device__ float g_z[(size_t)(T_SEQ + 1) * BATCH * F_HID];
__device__ float g_v[BATCH * F_HID];
__device__ float g_i[BATCH * F_HID];
__device__ float g_y[(size_t)T_SEQ * BATCH * F_OUT];

__global__ void init_state_kernel() {
    int idx = blockIdx.x * blockDim.x + threadIdx.x;
    if (idx < BATCH * F_HID) {
        g_v[idx] = 0.0f;
        g_i[idx] = 0.0f;
        g_z[idx] = 0.0f;
    }
}

// ---------------- input GEMM: g_zin = X @ Win^T, per-arm accumulation ----------------
// Arm1 (batch row < 128): 4 k-strided lanes (k mod 4), reduce (s0+s1)+(s2+s3).
// Arm2 (batch row >= 128): contiguous chain with KC2_2048 panels.
__global__ __launch_bounds__(256) void input_gemm_kernel(
    const float* __restrict__ X, const float* __restrict__ Win) {
    const int BM = 64, BN = 64, BK = 32;
    __shared__ float As[BK][BM + 1];
    __shared__ float Bs[BK][BN + 1];

    int m0 = blockIdx.y * BM;
    int n0 = blockIdx.x * BN;
    int tid = threadIdx.x;
    int tx = tid & 15;
    int ty = tid >> 4;
    int lr = tid >> 3;
    int lc = (tid & 7) * 4;

    bool arm1 = ((m0 & (BATCH - 1)) < 128);   // all 64 rows of the block share the arm

    float p[4][4][4] = {};   // arm1: [im][in][lane]
    float acc[4][4] = {};    // arm2 chain
    float tot[4][4] = {};    // arm2 panel totals

    for (int k0 = 0; k0 < F_IN; k0 += BK) {
#pragma unroll
        for (int rr = 0; rr < 2; rr++) {
            float4 a = *(const float4*)(X + (size_t)(m0 + lr + rr * 32) * F_IN + k0 + lc);
            As[lc + 0][lr + rr * 32] = a.x;
            As[lc + 1][lr + rr * 32] = a.y;
            As[lc + 2][lr + rr * 32] = a.z;
            As[lc + 3][lr + rr * 32] = a.w;
            float4 b = *(const float4*)(Win + (size_t)(n0 + lr + rr * 32) * F_IN + k0 + lc);
            Bs[lc + 0][lr + rr * 32] = b.x;
            Bs[lc + 1][lr + rr * 32] = b.y;
            Bs[lc + 2][lr + rr * 32] = b.z;
            Bs[lc + 3][lr + rr * 32] = b.w;
        }
        __syncthreads();
        if (arm1) {
#pragma unroll
            for (int k = 0; k < BK; k++) {
                float a[4], b[4];
#pragma unroll
                for (int i = 0; i < 4; i++) a[i] = As[k][ty * 4 + i];
#pragma unroll
                for (int i = 0; i < 4; i++) b[i] = Bs[k][tx * 4 + i];
#pragma unroll
                for (int im = 0; im < 4; im++)
#pragma unroll
                    for (int in = 0; in < 4; in++)
                        p[im][in][k & 3] = fmaf(a[im], b[in], p[im][in][k & 3]);
            }
        } else {
            int off = ((k0 + KC2_2048 - 1) / KC2_2048) * KC2_2048 - k0;
#pragma unroll
            for (int k = 0; k < BK; k++) {
                if (k == off) {
#pragma unroll
                    for (int im = 0; im < 4; im++)
#pragma unroll
                        for (int in = 0; in < 4; in++) {
                            tot[im][in] = __fadd_rn(tot[im][in], acc[im][in]);
                            acc[im][in] = 0.0f;
                        }
                }
                float a[4], b[4];
#pragma unroll
                for (int i = 0; i < 4; i++) a[i] = As[k][ty * 4 + i];
#pragma unroll
                for (int i = 0; i < 4; i++) b[i] = Bs[k][tx * 4 + i];
#pragma unroll
                for (int im = 0; im < 4; im++)
#pragma unroll
                    for (int in = 0; in < 4; in++)
                        acc[im][in] = fmaf(a[im], b[in], acc[im][in]);
            }
        }
        __syncthreads();
    }
#pragma unroll
    for (int im = 0; im < 4; im++) {
        float4 o;
        float r[4];
#pragma unroll
        for (int in = 0; in < 4; in++) {
            if (arm1)
                r[in] = __fadd_rn(__fadd_rn(p[im][in][0], p[im][in][1]),
                                  __fadd_rn(p[im][in][2], p[im][in][3]));
            else
                r[in] = __fadd_rn(tot[im][in], acc[im][in]);
        }
        o.x = r[0]; o.y = r[1]; o.z = r[2]; o.w = r[3];
        *(float4*)(g_zin + (size_t)(m0 + ty * 4 + im) * F_HID + n0 + tx * 4) = o;
    }
}

// ---------------- fused LIF step, per-arm dot accumulation ----------------
__global__ __launch_bounds__(256) void lif_step_kernel(
    const float* __restrict__ Wcin, const float* __restrict__ Wrec, int t) {
    const int BM = 32, BN = 64, BK = 32;
    __shared__ float As[BK][BM + 1];
    __shared__ float Bs[BK][BN + 1];

    int m0 = blockIdx.y * BM;
    int n0 = blockIdx.x * BN;
    int tid = threadIdx.x;
    int tx = tid & 15;
    int ty = tid >> 4;
    int lr = tid >> 3;
    int lc = (tid & 7) * 4;

    bool arm1 = (m0 < 128);   // block rows all on one side (m0 multiple of 32)

    float dot[2][2][4];

    const float* Ap[2];
    Ap[0] = g_zin + (size_t)t * BATCH * F_HID;
    Ap[1] = g_z   + (size_t)t * BATCH * F_HID;   // z_prev (slot t; slot 0 zeros)
    const float* Wp[2];
    Wp[0] = Wcin;
    Wp[1] = Wrec;

#pragma unroll 1
    for (int s = 0; s < 2; s++) {
        const float* A = Ap[s];
        const float* W = Wp[s];
        float p[2][4][4] = {};    // arm1 lanes
        float acc[2][4] = {};     // arm2 chain
        float tot[2][4] = {};     // arm2 panels
        for (int k0 = 0; k0 < F_HID; k0 += BK) {
            {
                float4 a = *(const float4*)(A + (size_t)(m0 + lr) * F_HID + k0 + lc);
                As[lc + 0][lr] = a.x;
                As[lc + 1][lr] = a.y;
                As[lc + 2][lr] = a.z;
                As[lc + 3][lr] = a.w;
            }
#pragma unroll
            for (int rr = 0; rr < 2; rr++) {
                float4 b = *(const float4*)(W + (size_t)(n0 + lr + rr * 32) * F_HID + k0 + lc);
                Bs[lc + 0][lr + rr * 32] = b.x;
                Bs[lc + 1][lr + rr * 32] = b.y;
                Bs[lc + 2][lr + rr * 32] = b.z;
                Bs[lc + 3][lr + rr * 32] = b.w;
            }
            __syncthreads();
            if (arm1) {
#pragma unroll
                for (int k = 0; k < BK; k++) {
                    float a[2], b[4];
                    a[0] = As[k][ty * 2 + 0];
                    a[1] = As[k][ty * 2 + 1];
#pragma unroll
                    for (int i = 0; i < 4; i++) b[i] = Bs[k][tx * 4 + i];
#pragma unroll
                    for (int im = 0; im < 2; im++)
#pragma unroll
                        for (int in = 0; in < 4; in++)
                            p[im][in][k & 3] = fmaf(a[im], b[in], p[im][in][k & 3]);
                }
            } else {
                int off = ((k0 + KC2_1024 - 1) / KC2_1024) * KC2_1024 - k0;
#pragma unroll
                for (int k = 0; k < BK; k++) {
                    if (k == off) {
#pragma unroll
                        for (int im = 0; im < 2; im++)
#pragma unroll
                            for (int in = 0; in < 4; in++) {
                                tot[im][in] = __fadd_rn(tot[im][in], acc[im][in]);
                                acc[im][in] = 0.0f;
                            }
                    }
                    float a[2], b[4];
                    a[0] = As[k][ty * 2 + 0];
                    a[1] = As[k][ty * 2 + 1];
#pragma unroll
                    for (int i = 0; i < 4; i++) b[i] = Bs[k][tx * 4 + i];
#pragma unroll
                    for (int im = 0; im < 2; im++)
#pragma unroll
                        for (int in = 0; in < 4; in++)
                            acc[im][in] = fmaf(a[im], b[in], acc[im][in]);
                }
            }
            __syncthreads();
        }
#pragma unroll
        for (int im = 0; im < 2; im++)
#pragma unroll
            for (int in = 0; in < 4; in++) {
                if (arm1)
                    dot[s][im][in] = __fadd_rn(__fadd_rn(p[im][in][0], p[im][in][1]),
                                               __fadd_rn(p[im][in][2], p[im][in][3]));
                else
                    dot[s][im][in] = __fadd_rn(tot[im][in], acc[im][in]);
            }
    }

    // epilogue: LIF state update (reference op order, no contraction)
    float* znew = g_z + (size_t)(t + 1) * BATCH * F_HID;
#pragma unroll
    for (int im = 0; im < 2; im++) {
        int m = m0 + ty * 2 + im;
        size_t base = (size_t)m * F_HID + n0 + tx * 4;
        float4 i4 = *(float4*)(g_i + base);
        float4 v4 = *(float4*)(g_v + base);
        float iv[4] = {i4.x, i4.y, i4.z, i4.w};
        float vv[4] = {v4.x, v4.y, v4.z, v4.w};
        float vn[4], in_[4], zf[4];
#pragma unroll
        for (int c = 0; c < 4; c++) {
            float t1 = __fadd_rn(-vv[c], iv[c]);
            float vdec = __fadd_rn(vv[c], __fmul_rn(0.1f, t1));
            float idec = __fmul_rn(iv[c], 0.8f);
            bool sp = vdec > 1.0f;
            zf[c] = sp ? 1.0f : 0.0f;
            vn[c] = sp ? 0.0f : vdec;
            in_[c] = __fadd_rn(__fadd_rn(idec, dot[0][im][c]), dot[1][im][c]);
        }
        *(float4*)(g_v + base) = make_float4(vn[0], vn[1], vn[2], vn[3]);
        *(float4*)(g_i + base) = make_float4(in_[0], in_[1], in_[2], in_[3]);
        *(float4*)(znew + base) = make_float4(zf[0], zf[1], zf[2], zf[3]);
    }
}

// ---------------- output projection: plain chain (linear stage, no flips) ----------------
__global__ __launch_bounds__(256) void out_gemm_kernel(const float* __restrict__ Wout) {
    const int BM = 64, BK = 32;
    __shared__ float As[BK][BM + 1];
    __shared__ float Ws[BK][F_OUT];

    int m0 = blockIdx.x * BM;
    int tid = threadIdx.x;
    int tx = tid & 31;
    int ty = tid >> 5;
    int lr = tid >> 3;
    int lc = (tid & 7) * 4;

    const float* Z = g_z + (size_t)BATCH * F_HID;
    float acc[8] = {};

    for (int k0 = 0; k0 < F_HID; k0 += BK) {
#pragma unroll
        for (int rr = 0; rr < 2; rr++) {
            float4 a = *(const float4*)(Z + (size_t)(m0 + lr + rr * 32) * F_HID + k0 + lc);
            As[lc + 0][lr + rr * 32] = a.x;
            As[lc + 1][lr + rr * 32] = a.y;
            As[lc + 2][lr + rr * 32] = a.z;
            As[lc + 3][lr + rr * 32] = a.w;
        }
        if (tid < 160) {
            int r = tid >> 3;
            int c = (tid & 7) * 4;
            float4 w = *(const float4*)(Wout + (size_t)r * F_HID + k0 + c);
            Ws[c + 0][r] = w.x;
            Ws[c + 1][r] = w.y;
            Ws[c + 2][r] = w.z;
            Ws[c + 3][r] = w.w;
        }
        __syncthreads();
#pragma unroll
        for (int k = 0; k < BK; k++) {
            float w = (tx < F_OUT) ? Ws[k][tx] : 0.0f;
#pragma unroll
            for (int im = 0; im < 8; im++)
                acc[im] = fmaf(As[k][ty + 8 * im], w, acc[im]);
        }
        __syncthreads();
    }
    if (tx < F_OUT) {
#pragma unroll
        for (int im = 0; im < 8; im++)
            g_y[(size_t)(m0 + ty + 8 * im) * F_OUT + tx] = acc[im];
    }
}

// ---------------- LI scan ----------------
__global__ void li_scan_kernel(float* __restrict__ out) {
    int id = blockIdx.x * blockDim.x + threadIdx.x;
    if (id >= BATCH * F_OUT) return;
    int b = id / F_OUT;
    int o = id - b * F_OUT;
    float vo = 0.0f, io = 0.0f;
#pragma unroll 4
    for (int t = 0; t < T_SEQ; t++) {
        float y = g_y[((size_t)t * BATCH + b) * F_OUT + o];
        float t1 = __fadd_rn(-vo, io);
        float vo_new = __fadd_rn(vo, __fmul_rn(0.1f, t1));
        io = __fadd_rn(__fmul_rn(io, 0.8f), y);
        vo = vo_new;
        out[((size_t)t * BATCH + b) * F_OUT + o] = vo_new;
    }
}

// ---------------- launch ----------------
extern "C" void kernel_launch(void* const* d_in, const int* in_sizes, int n_in,
                              void* d_out, int out_size) {
    const float* x     = (const float*)d_in[0];
    const float* W_in  = (const float*)d_in[1];
    const float* W_cin = (const float*)d_in[2];
    const float* W_rec = (const float*)d_in[3];
    const float* W_out = (const float*)d_in[4];
    float* out = (float*)d_out;

    init_state_kernel<<<(BATCH * F_HID + 255) / 256, 256>>>();

    dim3 ig_grid(F_HID / 64, (T_SEQ * BATCH) / 64);
    input_gemm_kernel<<<ig_grid, 256>>>(x, W_in);

    dim3 st_grid(F_HID / 64, BATCH / 32);
    for (int t = 0; t < T_SEQ; t++)
        lif_step_kernel<<<st_grid, 256>>>(W_cin, W_rec, t);

    out_gemm_kernel<<<(T_SEQ * BATCH) / 64, 256>>>(W_out);

    li_scan_kernel<<<(BATCH * F_OUT + 255) / 256, 256>>>(out);
}

// round 14
// speedup vs baseline: 1.4816x; 1.4816x over previous
#include <cuda_runtime.h>

#define T_SEQ 128
#define BATCH 256
#define F_IN  2048
#define F_HID 1024
#define F_OUT 20

// Arm 2 panel constants (frozen — part of the passing numeric configuration)
#define KC2_1024 520
#define KC2_2048 688

// ---------------- device scratch (no allocations allowed) ----------------
__device__ float g_zin[(size_t)T_SEQ * BATCH * F_HID];
__device__ float g_z[(size_t)(T_SEQ + 1) * BATCH * F_HID];
__device__ float g_v[BATCH * F_HID];
__device__ float g_i[BATCH * F_HID];
__device__ float g_y[(size_t)T_SEQ * BATCH * F_OUT];

__global__ void init_state_kernel() {
    int idx = blockIdx.x * blockDim.x + threadIdx.x;
    if (idx < BATCH * F_HID) {
        g_v[idx] = 0.0f;
        g_i[idx] = 0.0f;
        g_z[idx] = 0.0f;
    }
}

// ---------------- input GEMM: g_zin = X @ Win^T (double-buffered, math frozen) ----------------
__global__ __launch_bounds__(256) void input_gemm_kernel(
    const float* __restrict__ X, const float* __restrict__ Win) {
    const int BM = 64, BN = 64, BK = 32;
    const int NT = F_IN / BK;   // 64 tiles
    __shared__ float As[2][BK][BM + 1];
    __shared__ float Bs[2][BK][BN + 1];

    int m0 = blockIdx.y * BM;
    int n0 = blockIdx.x * BN;
    int tid = threadIdx.x;
    int tx = tid & 15;
    int ty = tid >> 4;
    int lr = tid >> 3;
    int lc = (tid & 7) * 4;

    bool arm1 = ((m0 & (BATCH - 1)) < 128);

    float p[4][4][4] = {};   // arm1 lanes
    float acc[4][4] = {};    // arm2 chain
    float tot[4][4] = {};    // arm2 panel totals

    // prefetch tile 0
    float4 ra0 = *(const float4*)(X + (size_t)(m0 + lr) * F_IN + lc);
    float4 ra1 = *(const float4*)(X + (size_t)(m0 + lr + 32) * F_IN + lc);
    float4 rb0 = *(const float4*)(Win + (size_t)(n0 + lr) * F_IN + lc);
    float4 rb1 = *(const float4*)(Win + (size_t)(n0 + lr + 32) * F_IN + lc);
    As[0][lc + 0][lr] = ra0.x; As[0][lc + 1][lr] = ra0.y; As[0][lc + 2][lr] = ra0.z; As[0][lc + 3][lr] = ra0.w;
    As[0][lc + 0][lr + 32] = ra1.x; As[0][lc + 1][lr + 32] = ra1.y; As[0][lc + 2][lr + 32] = ra1.z; As[0][lc + 3][lr + 32] = ra1.w;
    Bs[0][lc + 0][lr] = rb0.x; Bs[0][lc + 1][lr] = rb0.y; Bs[0][lc + 2][lr] = rb0.z; Bs[0][lc + 3][lr] = rb0.w;
    Bs[0][lc + 0][lr + 32] = rb1.x; Bs[0][lc + 1][lr + 32] = rb1.y; Bs[0][lc + 2][lr + 32] = rb1.z; Bs[0][lc + 3][lr + 32] = rb1.w;
    __syncthreads();

    for (int kt = 0; kt < NT; kt++) {
        int cur = kt & 1;
        int k0 = kt * BK;
        // prefetch next tile to registers
        if (kt + 1 < NT) {
            int kn = k0 + BK;
            ra0 = *(const float4*)(X + (size_t)(m0 + lr) * F_IN + kn + lc);
            ra1 = *(const float4*)(X + (size_t)(m0 + lr + 32) * F_IN + kn + lc);
            rb0 = *(const float4*)(Win + (size_t)(n0 + lr) * F_IN + kn + lc);
            rb1 = *(const float4*)(Win + (size_t)(n0 + lr + 32) * F_IN + kn + lc);
        }
        // compute on current buffer (arithmetic identical to R13)
        if (arm1) {
#pragma unroll
            for (int k = 0; k < BK; k++) {
                float a[4], b[4];
#pragma unroll
                for (int i = 0; i < 4; i++) a[i] = As[cur][k][ty * 4 + i];
#pragma unroll
                for (int i = 0; i < 4; i++) b[i] = Bs[cur][k][tx * 4 + i];
#pragma unroll
                for (int im = 0; im < 4; im++)
#pragma unroll
                    for (int in = 0; in < 4; in++)
                        p[im][in][k & 3] = fmaf(a[im], b[in], p[im][in][k & 3]);
            }
        } else {
            int off = ((k0 + KC2_2048 - 1) / KC2_2048) * KC2_2048 - k0;
#pragma unroll
            for (int k = 0; k < BK; k++) {
                if (k == off) {
#pragma unroll
                    for (int im = 0; im < 4; im++)
#pragma unroll
                        for (int in = 0; in < 4; in++) {
                            tot[im][in] = __fadd_rn(tot[im][in], acc[im][in]);
                            acc[im][in] = 0.0f;
                        }
                }
                float a[4], b[4];
#pragma unroll
                for (int i = 0; i < 4; i++) a[i] = As[cur][k][ty * 4 + i];
#pragma unroll
                for (int i = 0; i < 4; i++) b[i] = Bs[cur][k][tx * 4 + i];
#pragma unroll
                for (int im = 0; im < 4; im++)
#pragma unroll
                    for (int in = 0; in < 4; in++)
                        acc[im][in] = fmaf(a[im], b[in], acc[im][in]);
            }
        }
        // store next tile and single barrier
        if (kt + 1 < NT) {
            int nxt = cur ^ 1;
            As[nxt][lc + 0][lr] = ra0.x; As[nxt][lc + 1][lr] = ra0.y; As[nxt][lc + 2][lr] = ra0.z; As[nxt][lc + 3][lr] = ra0.w;
            As[nxt][lc + 0][lr + 32] = ra1.x; As[nxt][lc + 1][lr + 32] = ra1.y; As[nxt][lc + 2][lr + 32] = ra1.z; As[nxt][lc + 3][lr + 32] = ra1.w;
            Bs[nxt][lc + 0][lr] = rb0.x; Bs[nxt][lc + 1][lr] = rb0.y; Bs[nxt][lc + 2][lr] = rb0.z; Bs[nxt][lc + 3][lr] = rb0.w;
            Bs[nxt][lc + 0][lr + 32] = rb1.x; Bs[nxt][lc + 1][lr + 32] = rb1.y; Bs[nxt][lc + 2][lr + 32] = rb1.z; Bs[nxt][lc + 3][lr + 32] = rb1.w;
            __syncthreads();
        }
    }

#pragma unroll
    for (int im = 0; im < 4; im++) {
        float4 o;
        float r[4];
#pragma unroll
        for (int in = 0; in < 4; in++) {
            if (arm1)
                r[in] = __fadd_rn(__fadd_rn(p[im][in][0], p[im][in][1]),
                                  __fadd_rn(p[im][in][2], p[im][in][3]));
            else
                r[in] = __fadd_rn(tot[im][in], acc[im][in]);
        }
        o.x = r[0]; o.y = r[1]; o.z = r[2]; o.w = r[3];
        *(float4*)(g_zin + (size_t)(m0 + ty * 4 + im) * F_HID + n0 + tx * 4) = o;
    }
}

// ---------------- fused LIF step (double-buffered, math frozen) ----------------
__global__ __launch_bounds__(256) void lif_step_kernel(
    const float* __restrict__ Wcin, const float* __restrict__ Wrec, int t) {
    const int BM = 32, BN = 64, BK = 32;
    const int NT = F_HID / BK;   // 32 tiles
    __shared__ float As[2][BK][BM + 1];
    __shared__ float Bs[2][BK][BN + 1];

    int m0 = blockIdx.y * BM;
    int n0 = blockIdx.x * BN;
    int tid = threadIdx.x;
    int tx = tid & 15;
    int ty = tid >> 4;
    int lr = tid >> 3;
    int lc = (tid & 7) * 4;

    bool arm1 = (m0 < 128);

    float dot[2][2][4];

    const float* Ap[2];
    Ap[0] = g_zin + (size_t)t * BATCH * F_HID;
    Ap[1] = g_z   + (size_t)t * BATCH * F_HID;   // z_prev (slot t; slot 0 zeros)
    const float* Wp[2];
    Wp[0] = Wcin;
    Wp[1] = Wrec;

#pragma unroll 1
    for (int s = 0; s < 2; s++) {
        const float* A = Ap[s];
        const float* W = Wp[s];
        float p[2][4][4] = {};
        float acc[2][4] = {};
        float tot[2][4] = {};

        // prefetch tile 0
        float4 ra  = *(const float4*)(A + (size_t)(m0 + lr) * F_HID + lc);
        float4 rb0 = *(const float4*)(W + (size_t)(n0 + lr) * F_HID + lc);
        float4 rb1 = *(const float4*)(W + (size_t)(n0 + lr + 32) * F_HID + lc);
        As[0][lc + 0][lr] = ra.x; As[0][lc + 1][lr] = ra.y; As[0][lc + 2][lr] = ra.z; As[0][lc + 3][lr] = ra.w;
        Bs[0][lc + 0][lr] = rb0.x; Bs[0][lc + 1][lr] = rb0.y; Bs[0][lc + 2][lr] = rb0.z; Bs[0][lc + 3][lr] = rb0.w;
        Bs[0][lc + 0][lr + 32] = rb1.x; Bs[0][lc + 1][lr + 32] = rb1.y; Bs[0][lc + 2][lr + 32] = rb1.z; Bs[0][lc + 3][lr + 32] = rb1.w;
        __syncthreads();

        for (int kt = 0; kt < NT; kt++) {
            int cur = kt & 1;
            int k0 = kt * BK;
            if (kt + 1 < NT) {
                int kn = k0 + BK;
                ra  = *(const float4*)(A + (size_t)(m0 + lr) * F_HID + kn + lc);
                rb0 = *(const float4*)(W + (size_t)(n0 + lr) * F_HID + kn + lc);
                rb1 = *(const float4*)(W + (size_t)(n0 + lr + 32) * F_HID + kn + lc);
            }
            if (arm1) {
#pragma unroll
                for (int k = 0; k < BK; k++) {
                    float a[2], b[4];
                    a[0] = As[cur][k][ty * 2 + 0];
                    a[1] = As[cur][k][ty * 2 + 1];
#pragma unroll
                    for (int i = 0; i < 4; i++) b[i] = Bs[cur][k][tx * 4 + i];
#pragma unroll
                    for (int im = 0; im < 2; im++)
#pragma unroll
                        for (int in = 0; in < 4; in++)
                            p[im][in][k & 3] = fmaf(a[im], b[in], p[im][in][k & 3]);
                }
            } else {
                int off = ((k0 + KC2_1024 - 1) / KC2_1024) * KC2_1024 - k0;
#pragma unroll
                for (int k = 0; k < BK; k++) {
                    if (k == off) {
#pragma unroll
                        for (int im = 0; im < 2; im++)
#pragma unroll
                            for (int in = 0; in < 4; in++) {
                                tot[im][in] = __fadd_rn(tot[im][in], acc[im][in]);
                                acc[im][in] = 0.0f;
                            }
                    }
                    float a[2], b[4];
                    a[0] = As[cur][k][ty * 2 + 0];
                    a[1] = As[cur][k][ty * 2 + 1];
#pragma unroll
                    for (int i = 0; i < 4; i++) b[i] = Bs[cur][k][tx * 4 + i];
#pragma unroll
                    for (int im = 0; im < 2; im++)
#pragma unroll
                        for (int in = 0; in < 4; in++)
                            acc[im][in] = fmaf(a[im], b[in], acc[im][in]);
                }
            }
            if (kt + 1 < NT) {
                int nxt = cur ^ 1;
                As[nxt][lc + 0][lr] = ra.x; As[nxt][lc + 1][lr] = ra.y; As[nxt][lc + 2][lr] = ra.z; As[nxt][lc + 3][lr] = ra.w;
                Bs[nxt][lc + 0][lr] = rb0.x; Bs[nxt][lc + 1][lr] = rb0.y; Bs[nxt][lc + 2][lr] = rb0.z; Bs[nxt][lc + 3][lr] = rb0.w;
                Bs[nxt][lc + 0][lr + 32] = rb1.x; Bs[nxt][lc + 1][lr + 32] = rb1.y; Bs[nxt][lc + 2][lr + 32] = rb1.z; Bs[nxt][lc + 3][lr + 32] = rb1.w;
                __syncthreads();
            }
        }
        // barrier between sources: next source's initial store targets buf0 — ensure
        // all warps finished reading it (they did at tile NT-2) and finished tile NT-1.
        __syncthreads();

#pragma unroll
        for (int im = 0; im < 2; im++)
#pragma unroll
            for (int in = 0; in < 4; in++) {
                if (arm1)
                    dot[s][im][in] = __fadd_rn(__fadd_rn(p[im][in][0], p[im][in][1]),
                                               __fadd_rn(p[im][in][2], p[im][in][3]));
                else
                    dot[s][im][in] = __fadd_rn(tot[im][in], acc[im][in]);
            }
    }

    // epilogue: LIF state update (frozen)
    float* znew = g_z + (size_t)(t + 1) * BATCH * F_HID;
#pragma unroll
    for (int im = 0; im < 2; im++) {
        int m = m0 + ty * 2 + im;
        size_t base = (size_t)m * F_HID + n0 + tx * 4;
        float4 i4 = *(float4*)(g_i + base);
        float4 v4 = *(float4*)(g_v + base);
        float iv[4] = {i4.x, i4.y, i4.z, i4.w};
        float vv[4] = {v4.x, v4.y, v4.z, v4.w};
        float vn[4], in_[4], zf[4];
#pragma unroll
        for (int c = 0; c < 4; c++) {
            float t1 = __fadd_rn(-vv[c], iv[c]);
            float vdec = __fadd_rn(vv[c], __fmul_rn(0.1f, t1));
            float idec = __fmul_rn(iv[c], 0.8f);
            bool sp = vdec > 1.0f;
            zf[c] = sp ? 1.0f : 0.0f;
            vn[c] = sp ? 0.0f : vdec;
            in_[c] = __fadd_rn(__fadd_rn(idec, dot[0][im][c]), dot[1][im][c]);
        }
        *(float4*)(g_v + base) = make_float4(vn[0], vn[1], vn[2], vn[3]);
        *(float4*)(g_i + base) = make_float4(in_[0], in_[1], in_[2], in_[3]);
        *(float4*)(znew + base) = make_float4(zf[0], zf[1], zf[2], zf[3]);
    }
}

// ---------------- output projection: plain chain (frozen) ----------------
__global__ __launch_bounds__(256) void out_gemm_kernel(const float* __restrict__ Wout) {
    const int BM = 64, BK = 32;
    __shared__ float As[BK][BM + 1];
    __shared__ float Ws[BK][F_OUT];

    int m0 = blockIdx.x * BM;
    int tid = threadIdx.x;
    int tx = tid & 31;
    int ty = tid >> 5;
    int lr = tid >> 3;
    int lc = (tid & 7) * 4;

    const float* Z = g_z + (size_t)BATCH * F_HID;
    float acc[8] = {};

    for (int k0 = 0; k0 < F_HID; k0 += BK) {
#pragma unroll
        for (int rr = 0; rr < 2; rr++) {
            float4 a = *(const float4*)(Z + (size_t)(m0 + lr + rr * 32) * F_HID + k0 + lc);
            As[lc + 0][lr + rr * 32] = a.x;
            As[lc + 1][lr + rr * 32] = a.y;
            As[lc + 2][lr + rr * 32] = a.z;
            As[lc + 3][lr + rr * 32] = a.w;
        }
        if (tid < 160) {
            int r = tid >> 3;
            int c = (tid & 7) * 4;
            float4 w = *(const float4*)(Wout + (size_t)r * F_HID + k0 + c);
            Ws[c + 0][r] = w.x;
            Ws[c + 1][r] = w.y;
            Ws[c + 2][r] = w.z;
            Ws[c + 3][r] = w.w;
        }
        __syncthreads();
#pragma unroll
        for (int k = 0; k < BK; k++) {
            float w = (tx < F_OUT) ? Ws[k][tx] : 0.0f;
#pragma unroll
            for (int im = 0; im < 8; im++)
                acc[im] = fmaf(As[k][ty + 8 * im], w, acc[im]);
        }
        __syncthreads();
    }
    if (tx < F_OUT) {
#pragma unroll
        for (int im = 0; im < 8; im++)
            g_y[(size_t)(m0 + ty + 8 * im) * F_OUT + tx] = acc[im];
    }
}

// ---------------- LI scan (frozen) ----------------
__global__ void li_scan_kernel(float* __restrict__ out) {
    int id = blockIdx.x * blockDim.x + threadIdx.x;
    if (id >= BATCH * F_OUT) return;
    int b = id / F_OUT;
    int o = id - b * F_OUT;
    float vo = 0.0f, io = 0.0f;
#pragma unroll 4
    for (int t = 0; t < T_SEQ; t++) {
        float y = g_y[((size_t)t * BATCH + b) * F_OUT + o];
        float t1 = __fadd_rn(-vo, io);
        float vo_new = __fadd_rn(vo, __fmul_rn(0.1f, t1));
        io = __fadd_rn(__fmul_rn(io, 0.8f), y);
        vo = vo_new;
        out[((size_t)t * BATCH + b) * F_OUT + o] = vo_new;
    }
}

// ---------------- launch ----------------
extern "C" void kernel_launch(void* const* d_in, const int* in_sizes, int n_in,
                              void* d_out, int out_size) {
    const float* x     = (const float*)d_in[0];
    const float* W_in  = (const float*)d_in[1];
    const float* W_cin = (const float*)d_in[2];
    const float* W_rec = (const float*)d_in[3];
    const float* W_out = (const float*)d_in[4];
    float* out = (float*)d_out;

    init_state_kernel<<<(BATCH * F_HID + 255) / 256, 256>>>();

    dim3 ig_grid(F_HID / 64, (T_SEQ * BATCH) / 64);
    input_gemm_kernel<<<ig_grid, 256>>>(x, W_in);

    dim3 st_grid(F_HID / 64, BATCH / 32);
    for (int t = 0; t < T_SEQ; t++)
        lif_step_kernel<<<st_grid, 256>>>(W_cin, W_rec, t);

    out_gemm_kernel<<<(T_SEQ * BATCH) / 64, 256>>>(W_out);

    li_scan_kernel<<<(BATCH * F_OUT + 255) / 256, 256>>>(out);
}

// round 15
// speedup vs baseline: 1.8278x; 1.2337x over previous
#include <cuda_runtime.h>

#define T_SEQ 128
#define BATCH 256
#define F_IN  2048
#define F_HID 1024
#define F_OUT 20

// Arm 2 panel constants (frozen — part of the passing numeric configuration)
#define KC2_1024 520
#define KC2_2048 688

// ---------------- device scratch (no allocations allowed) ----------------
__device__ float g_zin[(size_t)T_SEQ * BATCH * F_HID];
__device__ float g_z[(size_t)(T_SEQ + 1) * BATCH * F_HID];
__device__ float g_v[BATCH * F_HID];
__device__ float g_i[BATCH * F_HID];
__device__ float g_y[(size_t)T_SEQ * BATCH * F_OUT];

__global__ void init_state_kernel() {
    int idx = blockIdx.x * blockDim.x + threadIdx.x;
    if (idx < BATCH * F_HID) {
        g_v[idx] = 0.0f;
        g_i[idx] = 0.0f;
        g_z[idx] = 0.0f;
    }
}

// ---------------- input GEMM: g_zin = X @ Win^T (double-buffered + vector LDS) ----------------
__global__ __launch_bounds__(256) void input_gemm_kernel(
    const float* __restrict__ X, const float* __restrict__ Win) {
    const int BM = 64, BN = 64, BK = 32;
    const int NT = F_IN / BK;        // 64 tiles
    const int PAD = 68;              // stride multiple of 4 -> float4 LDS
    __shared__ float As[2][BK][PAD];
    __shared__ float Bs[2][BK][PAD];

    int m0 = blockIdx.y * BM;
    int n0 = blockIdx.x * BN;
    int tid = threadIdx.x;
    int tx = tid & 15;
    int ty = tid >> 4;
    int lr = tid >> 3;
    int lc = (tid & 7) * 4;

    bool arm1 = ((m0 & (BATCH - 1)) < 128);

    float p[4][4][4] = {};   // arm1 lanes
    float acc[4][4] = {};    // arm2 chain
    float tot[4][4] = {};    // arm2 panel totals

    // prefetch tile 0
    float4 ra0 = *(const float4*)(X + (size_t)(m0 + lr) * F_IN + lc);
    float4 ra1 = *(const float4*)(X + (size_t)(m0 + lr + 32) * F_IN + lc);
    float4 rb0 = *(const float4*)(Win + (size_t)(n0 + lr) * F_IN + lc);
    float4 rb1 = *(const float4*)(Win + (size_t)(n0 + lr + 32) * F_IN + lc);
    As[0][lc + 0][lr] = ra0.x; As[0][lc + 1][lr] = ra0.y; As[0][lc + 2][lr] = ra0.z; As[0][lc + 3][lr] = ra0.w;
    As[0][lc + 0][lr + 32] = ra1.x; As[0][lc + 1][lr + 32] = ra1.y; As[0][lc + 2][lr + 32] = ra1.z; As[0][lc + 3][lr + 32] = ra1.w;
    Bs[0][lc + 0][lr] = rb0.x; Bs[0][lc + 1][lr] = rb0.y; Bs[0][lc + 2][lr] = rb0.z; Bs[0][lc + 3][lr] = rb0.w;
    Bs[0][lc + 0][lr + 32] = rb1.x; Bs[0][lc + 1][lr + 32] = rb1.y; Bs[0][lc + 2][lr + 32] = rb1.z; Bs[0][lc + 3][lr + 32] = rb1.w;
    __syncthreads();

    for (int kt = 0; kt < NT; kt++) {
        int cur = kt & 1;
        int k0 = kt * BK;
        if (kt + 1 < NT) {
            int kn = k0 + BK;
            ra0 = *(const float4*)(X + (size_t)(m0 + lr) * F_IN + kn + lc);
            ra1 = *(const float4*)(X + (size_t)(m0 + lr + 32) * F_IN + kn + lc);
            rb0 = *(const float4*)(Win + (size_t)(n0 + lr) * F_IN + kn + lc);
            rb1 = *(const float4*)(Win + (size_t)(n0 + lr + 32) * F_IN + kn + lc);
        }
        if (arm1) {
#pragma unroll
            for (int k = 0; k < BK; k++) {
                float4 av = *(const float4*)&As[cur][k][ty * 4];
                float4 bv = *(const float4*)&Bs[cur][k][tx * 4];
                float a[4] = {av.x, av.y, av.z, av.w};
                float b[4] = {bv.x, bv.y, bv.z, bv.w};
#pragma unroll
                for (int im = 0; im < 4; im++)
#pragma unroll
                    for (int in = 0; in < 4; in++)
                        p[im][in][k & 3] = fmaf(a[im], b[in], p[im][in][k & 3]);
            }
        } else {
            int off = ((k0 + KC2_2048 - 1) / KC2_2048) * KC2_2048 - k0;
#pragma unroll
            for (int k = 0; k < BK; k++) {
                if (k == off) {
#pragma unroll
                    for (int im = 0; im < 4; im++)
#pragma unroll
                        for (int in = 0; in < 4; in++) {
                            tot[im][in] = __fadd_rn(tot[im][in], acc[im][in]);
                            acc[im][in] = 0.0f;
                        }
                }
                float4 av = *(const float4*)&As[cur][k][ty * 4];
                float4 bv = *(const float4*)&Bs[cur][k][tx * 4];
                float a[4] = {av.x, av.y, av.z, av.w};
                float b[4] = {bv.x, bv.y, bv.z, bv.w};
#pragma unroll
                for (int im = 0; im < 4; im++)
#pragma unroll
                    for (int in = 0; in < 4; in++)
                        acc[im][in] = fmaf(a[im], b[in], acc[im][in]);
            }
        }
        if (kt + 1 < NT) {
            int nxt = cur ^ 1;
            As[nxt][lc + 0][lr] = ra0.x; As[nxt][lc + 1][lr] = ra0.y; As[nxt][lc + 2][lr] = ra0.z; As[nxt][lc + 3][lr] = ra0.w;
            As[nxt][lc + 0][lr + 32] = ra1.x; As[nxt][lc + 1][lr + 32] = ra1.y; As[nxt][lc + 2][lr + 32] = ra1.z; As[nxt][lc + 3][lr + 32] = ra1.w;
            Bs[nxt][lc + 0][lr] = rb0.x; Bs[nxt][lc + 1][lr] = rb0.y; Bs[nxt][lc + 2][lr] = rb0.z; Bs[nxt][lc + 3][lr] = rb0.w;
            Bs[nxt][lc + 0][lr + 32] = rb1.x; Bs[nxt][lc + 1][lr + 32] = rb1.y; Bs[nxt][lc + 2][lr + 32] = rb1.z; Bs[nxt][lc + 3][lr + 32] = rb1.w;
            __syncthreads();
        }
    }

#pragma unroll
    for (int im = 0; im < 4; im++) {
        float4 o;
        float r[4];
#pragma unroll
        for (int in = 0; in < 4; in++) {
            if (arm1)
                r[in] = __fadd_rn(__fadd_rn(p[im][in][0], p[im][in][1]),
                                  __fadd_rn(p[im][in][2], p[im][in][3]));
            else
                r[in] = __fadd_rn(tot[im][in], acc[im][in]);
        }
        o.x = r[0]; o.y = r[1]; o.z = r[2]; o.w = r[3];
        *(float4*)(g_zin + (size_t)(m0 + ty * 4 + im) * F_HID + n0 + tx * 4) = o;
    }
}

// ---------------- fused LIF step (double-buffered + vector LDS, math frozen) ----------------
__global__ __launch_bounds__(256) void lif_step_kernel(
    const float* __restrict__ Wcin, const float* __restrict__ Wrec, int t) {
    const int BM = 32, BN = 64, BK = 32;
    const int NT = F_HID / BK;       // 32 tiles
    const int PADA = 34;             // even stride -> float2 LDS for a
    const int PADB = 68;             // stride multiple of 4 -> float4 LDS for b
    __shared__ float As[2][BK][PADA];
    __shared__ float Bs[2][BK][PADB];

    int m0 = blockIdx.y * BM;
    int n0 = blockIdx.x * BN;
    int tid = threadIdx.x;
    int tx = tid & 15;
    int ty = tid >> 4;
    int lr = tid >> 3;
    int lc = (tid & 7) * 4;

    bool arm1 = (m0 < 128);

    float dot[2][2][4];

    const float* Ap[2];
    Ap[0] = g_zin + (size_t)t * BATCH * F_HID;
    Ap[1] = g_z   + (size_t)t * BATCH * F_HID;   // z_prev (slot t; slot 0 zeros)
    const float* Wp[2];
    Wp[0] = Wcin;
    Wp[1] = Wrec;

#pragma unroll 1
    for (int s = 0; s < 2; s++) {
        const float* A = Ap[s];
        const float* W = Wp[s];
        float p[2][4][4] = {};
        float acc[2][4] = {};
        float tot[2][4] = {};

        // prefetch tile 0
        float4 ra  = *(const float4*)(A + (size_t)(m0 + lr) * F_HID + lc);
        float4 rb0 = *(const float4*)(W + (size_t)(n0 + lr) * F_HID + lc);
        float4 rb1 = *(const float4*)(W + (size_t)(n0 + lr + 32) * F_HID + lc);
        As[0][lc + 0][lr] = ra.x; As[0][lc + 1][lr] = ra.y; As[0][lc + 2][lr] = ra.z; As[0][lc + 3][lr] = ra.w;
        Bs[0][lc + 0][lr] = rb0.x; Bs[0][lc + 1][lr] = rb0.y; Bs[0][lc + 2][lr] = rb0.z; Bs[0][lc + 3][lr] = rb0.w;
        Bs[0][lc + 0][lr + 32] = rb1.x; Bs[0][lc + 1][lr + 32] = rb1.y; Bs[0][lc + 2][lr + 32] = rb1.z; Bs[0][lc + 3][lr + 32] = rb1.w;
        __syncthreads();

        for (int kt = 0; kt < NT; kt++) {
            int cur = kt & 1;
            int k0 = kt * BK;
            if (kt + 1 < NT) {
                int kn = k0 + BK;
                ra  = *(const float4*)(A + (size_t)(m0 + lr) * F_HID + kn + lc);
                rb0 = *(const float4*)(W + (size_t)(n0 + lr) * F_HID + kn + lc);
                rb1 = *(const float4*)(W + (size_t)(n0 + lr + 32) * F_HID + kn + lc);
            }
            if (arm1) {
#pragma unroll
                for (int k = 0; k < BK; k++) {
                    float2 av = *(const float2*)&As[cur][k][ty * 2];
                    float4 bv = *(const float4*)&Bs[cur][k][tx * 4];
                    float a[2] = {av.x, av.y};
                    float b[4] = {bv.x, bv.y, bv.z, bv.w};
#pragma unroll
                    for (int im = 0; im < 2; im++)
#pragma unroll
                        for (int in = 0; in < 4; in++)
                            p[im][in][k & 3] = fmaf(a[im], b[in], p[im][in][k & 3]);
                }
            } else {
                int off = ((k0 + KC2_1024 - 1) / KC2_1024) * KC2_1024 - k0;
#pragma unroll
                for (int k = 0; k < BK; k++) {
                    if (k == off) {
#pragma unroll
                        for (int im = 0; im < 2; im++)
#pragma unroll
                            for (int in = 0; in < 4; in++) {
                                tot[im][in] = __fadd_rn(tot[im][in], acc[im][in]);
                                acc[im][in] = 0.0f;
                            }
                    }
                    float2 av = *(const float2*)&As[cur][k][ty * 2];
                    float4 bv = *(const float4*)&Bs[cur][k][tx * 4];
                    float a[2] = {av.x, av.y};
                    float b[4] = {bv.x, bv.y, bv.z, bv.w};
#pragma unroll
                    for (int im = 0; im < 2; im++)
#pragma unroll
                        for (int in = 0; in < 4; in++)
                            acc[im][in] = fmaf(a[im], b[in], acc[im][in]);
                }
            }
            if (kt + 1 < NT) {
                int nxt = cur ^ 1;
                As[nxt][lc + 0][lr] = ra.x; As[nxt][lc + 1][lr] = ra.y; As[nxt][lc + 2][lr] = ra.z; As[nxt][lc + 3][lr] = ra.w;
                Bs[nxt][lc + 0][lr] = rb0.x; Bs[nxt][lc + 1][lr] = rb0.y; Bs[nxt][lc + 2][lr] = rb0.z; Bs[nxt][lc + 3][lr] = rb0.w;
                Bs[nxt][lc + 0][lr + 32] = rb1.x; Bs[nxt][lc + 1][lr + 32] = rb1.y; Bs[nxt][lc + 2][lr + 32] = rb1.z; Bs[nxt][lc + 3][lr + 32] = rb1.w;
                __syncthreads();
            }
        }
        // no inter-source barrier needed: buf0's last reads (kt=30) completed
        // before the kt=30-end barrier; source s+1 tile0 store targets buf0,
        // and its own post-store __syncthreads orders it before compute.

#pragma unroll
        for (int im = 0; im < 2; im++)
#pragma unroll
            for (int in = 0; in < 4; in++) {
                if (arm1)
                    dot[s][im][in] = __fadd_rn(__fadd_rn(p[im][in][0], p[im][in][1]),
                                               __fadd_rn(p[im][in][2], p[im][in][3]));
                else
                    dot[s][im][in] = __fadd_rn(tot[im][in], acc[im][in]);
            }
    }

    // epilogue: LIF state update (frozen)
    float* znew = g_z + (size_t)(t + 1) * BATCH * F_HID;
#pragma unroll
    for (int im = 0; im < 2; im++) {
        int m = m0 + ty * 2 + im;
        size_t base = (size_t)m * F_HID + n0 + tx * 4;
        float4 i4 = *(float4*)(g_i + base);
        float4 v4 = *(float4*)(g_v + base);
        float iv[4] = {i4.x, i4.y, i4.z, i4.w};
        float vv[4] = {v4.x, v4.y, v4.z, v4.w};
        float vn[4], in_[4], zf[4];
#pragma unroll
        for (int c = 0; c < 4; c++) {
            float t1 = __fadd_rn(-vv[c], iv[c]);
            float vdec = __fadd_rn(vv[c], __fmul_rn(0.1f, t1));
            float idec = __fmul_rn(iv[c], 0.8f);
            bool sp = vdec > 1.0f;
            zf[c] = sp ? 1.0f : 0.0f;
            vn[c] = sp ? 0.0f : vdec;
            in_[c] = __fadd_rn(__fadd_rn(idec, dot[0][im][c]), dot[1][im][c]);
        }
        *(float4*)(g_v + base) = make_float4(vn[0], vn[1], vn[2], vn[3]);
        *(float4*)(g_i + base) = make_float4(in_[0], in_[1], in_[2], in_[3]);
        *(float4*)(znew + base) = make_float4(zf[0], zf[1], zf[2], zf[3]);
    }
}

// ---------------- output projection: plain chain (frozen) ----------------
__global__ __launch_bounds__(256) void out_gemm_kernel(const float* __restrict__ Wout) {
    const int BM = 64, BK = 32;
    __shared__ float As[BK][BM + 1];
    __shared__ float Ws[BK][F_OUT];

    int m0 = blockIdx.x * BM;
    int tid = threadIdx.x;
    int tx = tid & 31;
    int ty = tid >> 5;
    int lr = tid >> 3;
    int lc = (tid & 7) * 4;

    const float* Z = g_z + (size_t)BATCH * F_HID;
    float acc[8] = {};

    for (int k0 = 0; k0 < F_HID; k0 += BK) {
#pragma unroll
        for (int rr = 0; rr < 2; rr++) {
            float4 a = *(const float4*)(Z + (size_t)(m0 + lr + rr * 32) * F_HID + k0 + lc);
            As[lc + 0][lr + rr * 32] = a.x;
            As[lc + 1][lr + rr * 32] = a.y;
            As[lc + 2][lr + rr * 32] = a.z;
            As[lc + 3][lr + rr * 32] = a.w;
        }
        if (tid < 160) {
            int r = tid >> 3;
            int c = (tid & 7) * 4;
            float4 w = *(const float4*)(Wout + (size_t)r * F_HID + k0 + c);
            Ws[c + 0][r] = w.x;
            Ws[c + 1][r] = w.y;
            Ws[c + 2][r] = w.z;
            Ws[c + 3][r] = w.w;
        }
        __syncthreads();
#pragma unroll
        for (int k = 0; k < BK; k++) {
            float w = (tx < F_OUT) ? Ws[k][tx] : 0.0f;
#pragma unroll
            for (int im = 0; im < 8; im++)
                acc[im] = fmaf(As[k][ty + 8 * im], w, acc[im]);
        }
        __syncthreads();
    }
    if (tx < F_OUT) {
#pragma unroll
        for (int im = 0; im < 8; im++)
            g_y[(size_t)(m0 + ty + 8 * im) * F_OUT + tx] = acc[im];
    }
}

// ---------------- LI scan (frozen) ----------------
__global__ void li_scan_kernel(float* __restrict__ out) {
    int id = blockIdx.x * blockDim.x + threadIdx.x;
    if (id >= BATCH * F_OUT) return;
    int b = id / F_OUT;
    int o = id - b * F_OUT;
    float vo = 0.0f, io = 0.0f;
#pragma unroll 4
    for (int t = 0; t < T_SEQ; t++) {
        float y = g_y[((size_t)t * BATCH + b) * F_OUT + o];
        float t1 = __fadd_rn(-vo, io);
        float vo_new = __fadd_rn(vo, __fmul_rn(0.1f, t1));
        io = __fadd_rn(__fmul_rn(io, 0.8f), y);
        vo = vo_new;
        out[((size_t)t * BATCH + b) * F_OUT + o] = vo_new;
    }
}

// ---------------- launch ----------------
extern "C" void kernel_launch(void* const* d_in, const int* in_sizes, int n_in,
                              void* d_out, int out_size) {
    const float* x     = (const float*)d_in[0];
    const float* W_in  = (const float*)d_in[1];
    const float* W_cin = (const float*)d_in[2];
    const float* W_rec = (const float*)d_in[3];
    const float* W_out = (const float*)d_in[4];
    float* out = (float*)d_out;

    init_state_kernel<<<(BATCH * F_HID + 255) / 256, 256>>>();

    dim3 ig_grid(F_HID / 64, (T_SEQ * BATCH) / 64);
    input_gemm_kernel<<<ig_grid, 256>>>(x, W_in);

    dim3 st_grid(F_HID / 64, BATCH / 32);
    for (int t = 0; t < T_SEQ; t++)
        lif_step_kernel<<<st_grid, 256>>>(W_cin, W_rec, t);

    out_gemm_kernel<<<(T_SEQ * BATCH) / 64, 256>>>(W_out);

    li_scan_kernel<<<(BATCH * F_OUT + 255) / 256, 256>>>(out);
}

// round 16
// speedup vs baseline: 1.8403x; 1.0068x over previous
#include <cuda_runtime.h>

#define T_SEQ 128
#define BATCH 256
#define F_IN  2048
#define F_HID 1024
#define F_OUT 20

// Arm 2 panel constants (frozen — part of the passing numeric configuration)
#define KC2_1024 520
#define KC2_2048 688

// ---------------- device scratch (no allocations allowed) ----------------
__device__ float g_zin[(size_t)T_SEQ * BATCH * F_HID];
__device__ float g_z[(size_t)(T_SEQ + 1) * BATCH * F_HID];
__device__ float g_v[BATCH * F_HID];
__device__ float g_i[BATCH * F_HID];
__device__ float g_y[(size_t)T_SEQ * BATCH * F_OUT];

__global__ void init_state_kernel() {
    int idx = blockIdx.x * blockDim.x + threadIdx.x;
    if (idx < BATCH * F_HID) {
        g_v[idx] = 0.0f;
        g_i[idx] = 0.0f;
        g_z[idx] = 0.0f;
    }
}

// ---------------- input GEMM: g_zin = X @ Win^T (unchanged from R15 — at FMA floor) ----------------
__global__ __launch_bounds__(256) void input_gemm_kernel(
    const float* __restrict__ X, const float* __restrict__ Win) {
    const int BM = 64, BN = 64, BK = 32;
    const int NT = F_IN / BK;
    const int PAD = 68;
    __shared__ float As[2][BK][PAD];
    __shared__ float Bs[2][BK][PAD];

    int m0 = blockIdx.y * BM;
    int n0 = blockIdx.x * BN;
    int tid = threadIdx.x;
    int tx = tid & 15;
    int ty = tid >> 4;
    int lr = tid >> 3;
    int lc = (tid & 7) * 4;

    bool arm1 = ((m0 & (BATCH - 1)) < 128);

    float p[4][4][4] = {};
    float acc[4][4] = {};
    float tot[4][4] = {};

    float4 ra0 = *(const float4*)(X + (size_t)(m0 + lr) * F_IN + lc);
    float4 ra1 = *(const float4*)(X + (size_t)(m0 + lr + 32) * F_IN + lc);
    float4 rb0 = *(const float4*)(Win + (size_t)(n0 + lr) * F_IN + lc);
    float4 rb1 = *(const float4*)(Win + (size_t)(n0 + lr + 32) * F_IN + lc);
    As[0][lc + 0][lr] = ra0.x; As[0][lc + 1][lr] = ra0.y; As[0][lc + 2][lr] = ra0.z; As[0][lc + 3][lr] = ra0.w;
    As[0][lc + 0][lr + 32] = ra1.x; As[0][lc + 1][lr + 32] = ra1.y; As[0][lc + 2][lr + 32] = ra1.z; As[0][lc + 3][lr + 32] = ra1.w;
    Bs[0][lc + 0][lr] = rb0.x; Bs[0][lc + 1][lr] = rb0.y; Bs[0][lc + 2][lr] = rb0.z; Bs[0][lc + 3][lr] = rb0.w;
    Bs[0][lc + 0][lr + 32] = rb1.x; Bs[0][lc + 1][lr + 32] = rb1.y; Bs[0][lc + 2][lr + 32] = rb1.z; Bs[0][lc + 3][lr + 32] = rb1.w;
    __syncthreads();

    for (int kt = 0; kt < NT; kt++) {
        int cur = kt & 1;
        int k0 = kt * BK;
        if (kt + 1 < NT) {
            int kn = k0 + BK;
            ra0 = *(const float4*)(X + (size_t)(m0 + lr) * F_IN + kn + lc);
            ra1 = *(const float4*)(X + (size_t)(m0 + lr + 32) * F_IN + kn + lc);
            rb0 = *(const float4*)(Win + (size_t)(n0 + lr) * F_IN + kn + lc);
            rb1 = *(const float4*)(Win + (size_t)(n0 + lr + 32) * F_IN + kn + lc);
        }
        if (arm1) {
#pragma unroll
            for (int k = 0; k < BK; k++) {
                float4 av = *(const float4*)&As[cur][k][ty * 4];
                float4 bv = *(const float4*)&Bs[cur][k][tx * 4];
                float a[4] = {av.x, av.y, av.z, av.w};
                float b[4] = {bv.x, bv.y, bv.z, bv.w};
#pragma unroll
                for (int im = 0; im < 4; im++)
#pragma unroll
                    for (int in = 0; in < 4; in++)
                        p[im][in][k & 3] = fmaf(a[im], b[in], p[im][in][k & 3]);
            }
        } else {
            int off = ((k0 + KC2_2048 - 1) / KC2_2048) * KC2_2048 - k0;
#pragma unroll
            for (int k = 0; k < BK; k++) {
                if (k == off) {
#pragma unroll
                    for (int im = 0; im < 4; im++)
#pragma unroll
                        for (int in = 0; in < 4; in++) {
                            tot[im][in] = __fadd_rn(tot[im][in], acc[im][in]);
                            acc[im][in] = 0.0f;
                        }
                }
                float4 av = *(const float4*)&As[cur][k][ty * 4];
                float4 bv = *(const float4*)&Bs[cur][k][tx * 4];
                float a[4] = {av.x, av.y, av.z, av.w};
                float b[4] = {bv.x, bv.y, bv.z, bv.w};
#pragma unroll
                for (int im = 0; im < 4; im++)
#pragma unroll
                    for (int in = 0; in < 4; in++)
                        acc[im][in] = fmaf(a[im], b[in], acc[im][in]);
            }
        }
        if (kt + 1 < NT) {
            int nxt = cur ^ 1;
            As[nxt][lc + 0][lr] = ra0.x; As[nxt][lc + 1][lr] = ra0.y; As[nxt][lc + 2][lr] = ra0.z; As[nxt][lc + 3][lr] = ra0.w;
            As[nxt][lc + 0][lr + 32] = ra1.x; As[nxt][lc + 1][lr + 32] = ra1.y; As[nxt][lc + 2][lr + 32] = ra1.z; As[nxt][lc + 3][lr + 32] = ra1.w;
            Bs[nxt][lc + 0][lr] = rb0.x; Bs[nxt][lc + 1][lr] = rb0.y; Bs[nxt][lc + 2][lr] = rb0.z; Bs[nxt][lc + 3][lr] = rb0.w;
            Bs[nxt][lc + 0][lr + 32] = rb1.x; Bs[nxt][lc + 1][lr + 32] = rb1.y; Bs[nxt][lc + 2][lr + 32] = rb1.z; Bs[nxt][lc + 3][lr + 32] = rb1.w;
            __syncthreads();
        }
    }

#pragma unroll
    for (int im = 0; im < 4; im++) {
        float4 o;
        float r[4];
#pragma unroll
        for (int in = 0; in < 4; in++) {
            if (arm1)
                r[in] = __fadd_rn(__fadd_rn(p[im][in][0], p[im][in][1]),
                                  __fadd_rn(p[im][in][2], p[im][in][3]));
            else
                r[in] = __fadd_rn(tot[im][in], acc[im][in]);
        }
        o.x = r[0]; o.y = r[1]; o.z = r[2]; o.w = r[3];
        *(float4*)(g_zin + (size_t)(m0 + ty * 4 + im) * F_HID + n0 + tx * 4) = o;
    }
}

// ---------------- fused LIF step: warp-uniform A broadcast (math frozen) ----------------
// Thread map: lane=tid&31 -> n = n0 + lane*2 + {0,1}; warp=tid>>5 -> m = m0 + warp*4 + {0..3}.
// Per k: a = float4 broadcast (1 wf), b = float2 (2 wf) -> LDS under FMA floor.
__global__ __launch_bounds__(256) void lif_step_kernel(
    const float* __restrict__ Wcin, const float* __restrict__ Wrec, int t) {
    const int BM = 32, BN = 64, BK = 32;
    const int NT = F_HID / BK;
    const int PADA = 36;             // multiple of 4 -> float4 LDS for a
    const int PADB = 66;             // even -> float2 LDS for b
    __shared__ float As[2][BK][PADA];
    __shared__ float Bs[2][BK][PADB];

    int m0 = blockIdx.y * BM;
    int n0 = blockIdx.x * BN;
    int tid = threadIdx.x;
    int lane = tid & 31;
    int warp = tid >> 5;
    int lr = tid >> 3;
    int lc = (tid & 7) * 4;

    bool arm1 = (m0 < 128);

    float dot[2][4][2];

    const float* Ap[2];
    Ap[0] = g_zin + (size_t)t * BATCH * F_HID;
    Ap[1] = g_z   + (size_t)t * BATCH * F_HID;   // z_prev (slot t; slot 0 zeros)
    const float* Wp[2];
    Wp[0] = Wcin;
    Wp[1] = Wrec;

#pragma unroll 1
    for (int s = 0; s < 2; s++) {
        const float* A = Ap[s];
        const float* W = Wp[s];
        float p[4][2][4] = {};
        float acc[4][2] = {};
        float tot[4][2] = {};

        // prefetch tile 0 (store pattern unchanged)
        float4 ra  = *(const float4*)(A + (size_t)(m0 + lr) * F_HID + lc);
        float4 rb0 = *(const float4*)(W + (size_t)(n0 + lr) * F_HID + lc);
        float4 rb1 = *(const float4*)(W + (size_t)(n0 + lr + 32) * F_HID + lc);
        As[0][lc + 0][lr] = ra.x; As[0][lc + 1][lr] = ra.y; As[0][lc + 2][lr] = ra.z; As[0][lc + 3][lr] = ra.w;
        Bs[0][lc + 0][lr] = rb0.x; Bs[0][lc + 1][lr] = rb0.y; Bs[0][lc + 2][lr] = rb0.z; Bs[0][lc + 3][lr] = rb0.w;
        Bs[0][lc + 0][lr + 32] = rb1.x; Bs[0][lc + 1][lr + 32] = rb1.y; Bs[0][lc + 2][lr + 32] = rb1.z; Bs[0][lc + 3][lr + 32] = rb1.w;
        __syncthreads();

        for (int kt = 0; kt < NT; kt++) {
            int cur = kt & 1;
            int k0 = kt * BK;
            if (kt + 1 < NT) {
                int kn = k0 + BK;
                ra  = *(const float4*)(A + (size_t)(m0 + lr) * F_HID + kn + lc);
                rb0 = *(const float4*)(W + (size_t)(n0 + lr) * F_HID + kn + lc);
                rb1 = *(const float4*)(W + (size_t)(n0 + lr + 32) * F_HID + kn + lc);
            }
            if (arm1) {
#pragma unroll
                for (int k = 0; k < BK; k++) {
                    float4 av = *(const float4*)&As[cur][k][warp * 4];   // broadcast
                    float2 bv = *(const float2*)&Bs[cur][k][lane * 2];
                    float a[4] = {av.x, av.y, av.z, av.w};
                    float b[2] = {bv.x, bv.y};
#pragma unroll
                    for (int im = 0; im < 4; im++)
#pragma unroll
                        for (int in = 0; in < 2; in++)
                            p[im][in][k & 3] = fmaf(a[im], b[in], p[im][in][k & 3]);
                }
            } else {
                int off = ((k0 + KC2_1024 - 1) / KC2_1024) * KC2_1024 - k0;
#pragma unroll
                for (int k = 0; k < BK; k++) {
                    if (k == off) {
#pragma unroll
                        for (int im = 0; im < 4; im++)
#pragma unroll
                            for (int in = 0; in < 2; in++) {
                                tot[im][in] = __fadd_rn(tot[im][in], acc[im][in]);
                                acc[im][in] = 0.0f;
                            }
                    }
                    float4 av = *(const float4*)&As[cur][k][warp * 4];
                    float2 bv = *(const float2*)&Bs[cur][k][lane * 2];
                    float a[4] = {av.x, av.y, av.z, av.w};
                    float b[2] = {bv.x, bv.y};
#pragma unroll
                    for (int im = 0; im < 4; im++)
#pragma unroll
                        for (int in = 0; in < 2; in++)
                            acc[im][in] = fmaf(a[im], b[in], acc[im][in]);
                }
            }
            if (kt + 1 < NT) {
                int nxt = cur ^ 1;
                As[nxt][lc + 0][lr] = ra.x; As[nxt][lc + 1][lr] = ra.y; As[nxt][lc + 2][lr] = ra.z; As[nxt][lc + 3][lr] = ra.w;
                Bs[nxt][lc + 0][lr] = rb0.x; Bs[nxt][lc + 1][lr] = rb0.y; Bs[nxt][lc + 2][lr] = rb0.z; Bs[nxt][lc + 3][lr] = rb0.w;
                Bs[nxt][lc + 0][lr + 32] = rb1.x; Bs[nxt][lc + 1][lr + 32] = rb1.y; Bs[nxt][lc + 2][lr + 32] = rb1.z; Bs[nxt][lc + 3][lr + 32] = rb1.w;
                __syncthreads();
            }
        }

#pragma unroll
        for (int im = 0; im < 4; im++)
#pragma unroll
            for (int in = 0; in < 2; in++) {
                if (arm1)
                    dot[s][im][in] = __fadd_rn(__fadd_rn(p[im][in][0], p[im][in][1]),
                                               __fadd_rn(p[im][in][2], p[im][in][3]));
                else
                    dot[s][im][in] = __fadd_rn(tot[im][in], acc[im][in]);
            }
    }

    // epilogue: LIF state update (frozen expressions, float2 granularity)
    float* znew = g_z + (size_t)(t + 1) * BATCH * F_HID;
#pragma unroll
    for (int im = 0; im < 4; im++) {
        int m = m0 + warp * 4 + im;
        size_t base = (size_t)m * F_HID + n0 + lane * 2;
        float2 i2 = *(float2*)(g_i + base);
        float2 v2 = *(float2*)(g_v + base);
        float iv[2] = {i2.x, i2.y};
        float vv[2] = {v2.x, v2.y};
        float vn[2], in_[2], zf[2];
#pragma unroll
        for (int c = 0; c < 2; c++) {
            float t1 = __fadd_rn(-vv[c], iv[c]);
            float vdec = __fadd_rn(vv[c], __fmul_rn(0.1f, t1));
            float idec = __fmul_rn(iv[c], 0.8f);
            bool sp = vdec > 1.0f;
            zf[c] = sp ? 1.0f : 0.0f;
            vn[c] = sp ? 0.0f : vdec;
            in_[c] = __fadd_rn(__fadd_rn(idec, dot[0][im][c]), dot[1][im][c]);
        }
        *(float2*)(g_v + base) = make_float2(vn[0], vn[1]);
        *(float2*)(g_i + base) = make_float2(in_[0], in_[1]);
        *(float2*)(znew + base) = make_float2(zf[0], zf[1]);
    }
}

// ---------------- output projection: plain chain (frozen) ----------------
__global__ __launch_bounds__(256) void out_gemm_kernel(const float* __restrict__ Wout) {
    const int BM = 64, BK = 32;
    __shared__ float As[BK][BM + 1];
    __shared__ float Ws[BK][F_OUT];

    int m0 = blockIdx.x * BM;
    int tid = threadIdx.x;
    int tx = tid & 31;
    int ty = tid >> 5;
    int lr = tid >> 3;
    int lc = (tid & 7) * 4;

    const float* Z = g_z + (size_t)BATCH * F_HID;
    float acc[8] = {};

    for (int k0 = 0; k0 < F_HID; k0 += BK) {
#pragma unroll
        for (int rr = 0; rr < 2; rr++) {
            float4 a = *(const float4*)(Z + (size_t)(m0 + lr + rr * 32) * F_HID + k0 + lc);
            As[lc + 0][lr + rr * 32] = a.x;
            As[lc + 1][lr + rr * 32] = a.y;
            As[lc + 2][lr + rr * 32] = a.z;
            As[lc + 3][lr + rr * 32] = a.w;
        }
        if (tid < 160) {
            int r = tid >> 3;
            int c = (tid & 7) * 4;
            float4 w = *(const float4*)(Wout + (size_t)r * F_HID + k0 + c);
            Ws[c + 0][r] = w.x;
            Ws[c + 1][r] = w.y;
            Ws[c + 2][r] = w.z;
            Ws[c + 3][r] = w.w;
        }
        __syncthreads();
#pragma unroll
        for (int k = 0; k < BK; k++) {
            float w = (tx < F_OUT) ? Ws[k][tx] : 0.0f;
#pragma unroll
            for (int im = 0; im < 8; im++)
                acc[im] = fmaf(As[k][ty + 8 * im], w, acc[im]);
        }
        __syncthreads();
    }
    if (tx < F_OUT) {
#pragma unroll
        for (int im = 0; im < 8; im++)
            g_y[(size_t)(m0 + ty + 8 * im) * F_OUT + tx] = acc[im];
    }
}

// ---------------- LI scan (frozen) ----------------
__global__ void li_scan_kernel(float* __restrict__ out) {
    int id = blockIdx.x * blockDim.x + threadIdx.x;
    if (id >= BATCH * F_OUT) return;
    int b = id / F_OUT;
    int o = id - b * F_OUT;
    float vo = 0.0f, io = 0.0f;
#pragma unroll 4
    for (int t = 0; t < T_SEQ; t++) {
        float y = g_y[((size_t)t * BATCH + b) * F_OUT + o];
        float t1 = __fadd_rn(-vo, io);
        float vo_new = __fadd_rn(vo, __fmul_rn(0.1f, t1));
        io = __fadd_rn(__fmul_rn(io, 0.8f), y);
        vo = vo_new;
        out[((size_t)t * BATCH + b) * F_OUT + o] = vo_new;
    }
}

// ---------------- launch ----------------
extern "C" void kernel_launch(void* const* d_in, const int* in_sizes, int n_in,
                              void* d_out, int out_size) {
    const float* x     = (const float*)d_in[0];
    const float* W_in  = (const float*)d_in[1];
    const float* W_cin = (const float*)d_in[2];
    const float* W_rec = (const float*)d_in[3];
    const float* W_out = (const float*)d_in[4];
    float* out = (float*)d_out;

    init_state_kernel<<<(BATCH * F_HID + 255) / 256, 256>>>();

    dim3 ig_grid(F_HID / 64, (T_SEQ * BATCH) / 64);
    input_gemm_kernel<<<ig_grid, 256>>>(x, W_in);

    dim3 st_grid(F_HID / 64, BATCH / 32);
    for (int t = 0; t < T_SEQ; t++)
        lif_step_kernel<<<st_grid, 256>>>(W_cin, W_rec, t);

    out_gemm_kernel<<<(T_SEQ * BATCH) / 64, 256>>>(W_out);

    li_scan_kernel<<<(BATCH * F_OUT + 255) / 256, 256>>>(out);
}